// round 16
// baseline (speedup 1.0000x reference)
#include <cuda_runtime.h>
#include <math.h>

#define NTHREADS 128
#define COUNT_SHIFT 52
#define SUM_MASK ((1ULL << COUNT_SHIFT) - 1ULL)
#define FP_SCALE 1073741824.0f  /* 2^30 */

// Packed accumulator: bits[52:64) = block arrival count, bits[0:52) = fixed-point sum.
__device__ unsigned long long g_acc = 0ULL;

__device__ __forceinline__ float2 ldg_nc2(const float* p) {
    float2 v;
    asm volatile("ld.global.nc.v2.f32 {%0,%1}, [%2];"
                 : "=f"(v.x), "=f"(v.y) : "l"(p));
    return v;
}

__global__ void __launch_bounds__(NTHREADS)
smpl_fused_kernel(const float* __restrict__ corr,
                  const float* __restrict__ gt,
                  const float* __restrict__ vis,
                  float* __restrict__ out,
                  int total, int hw_shift, int h, int w, double final_scale) {
    const int hw = 1 << hw_shift;
    float acc = 0.0f;

    const int t = blockIdx.x * NTHREADS + threadIdx.x;
    if (t < total) {
        const int b = t >> hw_shift;
        const int p = t & (hw - 1);

        const float g0 = __ldg(gt + (size_t)b * 2 * hw + p);       // channel 0 -> x
        const float g1 = __ldg(gt + (size_t)b * 2 * hw + hw + p);  // channel 1 -> y
        const float v  = __ldg(vis + (size_t)b * hw + p);

        const float gx = (g0 + 1.0f) * (float)(w - 1) * 0.5f;
        const float gy = (g1 + 1.0f) * (float)(h - 1) * 0.5f;
        const float fx = floorf(gx);
        const float fy = floorf(gy);

        const float wy0 = fy + 1.0f - gy;
        const float wy1 = gy - fy;
        const float wx0 = fx + 1.0f - gx;
        const float wx1 = gx - fx;

        const float wt0 = wy0 * wx0;
        const float wt1 = wy0 * wx1;
        const float wt2 = wy1 * wx0;
        const float wt3 = wy1 * wx1;

        // clamped row/col indices (clip in float then cast, matching reference)
        const float x0f = fminf(fmaxf(fy,        0.0f), (float)(h - 1));
        const float x1f = fminf(fmaxf(fy + 1.0f, 0.0f), (float)(h - 1));
        const float y0f = fminf(fmaxf(fx,        0.0f), (float)(w - 1));
        const float y1f = fminf(fmaxf(fx + 1.0f, 0.0f), (float)(w - 1));
        const int x0 = (int)x0f, x1 = (int)x1f;
        const int y0 = (int)y0f, y1 = (int)y1f;

        const float* __restrict__ base0 = corr + ((size_t)b * hw + p) * hw + x0 * w;
        const float* __restrict__ base1 = corr + ((size_t)b * hw + p) * hw + x1 * w;

        float c0, c1, c2, c3;
        // Fast path: adjacent columns, 8B-aligned -> 2x LDG.64 (one wavefront each).
        if ((y1 == y0 + 1) && ((y0 & 1) == 0)) {
            const float2 a  = ldg_nc2(base0 + y0);
            const float2 bb = ldg_nc2(base1 + y0);
            c0 = a.x; c1 = a.y; c2 = bb.x; c3 = bb.y;
        } else {
            c0 = __ldg(base0 + y0);
            c1 = __ldg(base0 + y1);
            c2 = __ldg(base1 + y0);
            c3 = __ldg(base1 + y1);
        }

        // |c*v - wt*v| = v * |c - wt|  (vis mask is non-negative)
        const float s01 = fabsf(c0 - wt0) + fabsf(c1 - wt1);
        const float s23 = fabsf(c2 - wt2) + fabsf(c3 - wt3);
        acc = v * (s01 + s23);
    }

    // Block reduction: warp shuffles -> shared (4 warps) -> warp 0 -> ONE atomic.
    __shared__ float smem[NTHREADS / 32];
    const int lane = threadIdx.x & 31;
    const int wid  = threadIdx.x >> 5;
    #pragma unroll
    for (int off = 16; off > 0; off >>= 1)
        acc += __shfl_down_sync(0xFFFFFFFFu, acc, off);
    if (lane == 0) smem[wid] = acc;
    __syncthreads();
    if (wid == 0) {
        float s = (lane < (NTHREADS >> 5)) ? smem[lane] : 0.0f;
        // 4 partials -> 2 shuffle steps
        #pragma unroll
        for (int off = 2; off > 0; off >>= 1)
            s += __shfl_down_sync(0xFFFFFFFFu, s, off);
        if (lane == 0) {
            // One packed atomic: count in high bits, fixed-point sum in low bits.
            const unsigned long long q =
                (unsigned long long)__float2ull_rn(s * FP_SCALE);
            const unsigned long long pack = (1ULL << COUNT_SHIFT) | q;
            const unsigned long long old = atomicAdd(&g_acc, pack);
            const unsigned int cnt = (unsigned int)(old >> COUNT_SHIFT);
            if (cnt == gridDim.x - 1) {
                const unsigned long long tot = (old & SUM_MASK) + q;
                out[0] = (float)((double)tot * final_scale);
                atomicExch(&g_acc, 0ULL);  // reset for next graph replay
            }
        }
    }
}

extern "C" void kernel_launch(void* const* d_in, const int* in_sizes, int n_in,
                              void* d_out, int out_size) {
    const float* corr = (const float*)d_in[0];  // [B, h*w, h*w]
    const float* gt   = (const float*)d_in[1];  // [B, 2, h, w]
    const float* vis  = (const float*)d_in[2];  // [B, 1, h, w]
    float* out = (float*)d_out;

    const long long n_corr = in_sizes[0];
    const long long n_vis  = in_sizes[2];
    const int hw = (int)(n_corr / n_vis);
    const int B  = (int)(n_vis / hw);
    int h = 1;
    while (h * h < hw) h++;
    const int w = h;

    int hw_shift = 0;
    while ((1 << hw_shift) < hw) hw_shift++;

    const int total = B * hw;
    const double final_scale =
        (1.0 / (double)FP_SCALE) * (1.0 / (4.0 * (double)total));

    const int grid = (total + NTHREADS - 1) / NTHREADS;   // 512 (exact) for 65536

    smpl_fused_kernel<<<grid, NTHREADS>>>(corr, gt, vis, out,
                                          total, hw_shift, h, w, final_scale);
}